// round 9
// baseline (speedup 1.0000x reference)
#include <cuda_runtime.h>

#define NBLK   10
#define NBATCH 2048
#define NCH    64
#define NSKIP  96
#define TILE   32
#define NCTA   (NBATCH/TILE)           /* 64 */
#define NCOLS  1023
#define CURP   68                      /* padded row stride for cur/del/z */
#define SSP    100                     /* padded row stride for skip/h */
#define NBUF   ((size_t)NBATCH*NCH*NCOLS)   /* 134086656 */

__device__ float g_currents[NBLK * NBATCH * NCH];

#define FMA4(acc, s, v) do { (acc)[0] += (s)*(v).x; (acc)[1] += (s)*(v).y; \
                             (acc)[2] += (s)*(v).z; (acc)[3] += (s)*(v).w; } while(0)

// ---------------------------------------------------------------------------
// Compute kernel: 64 CTAs x 256 threads. CTA owns 32 samples.
// Thread = (sp 0..15, tg 0..15): 2 samples x 4 channels (proven per-thread
// shape). ALL weights resident (single-phase staging, 3 barriers/block).
// Head scratch (ssm/hsm) aliases the dead del region after the block loop.
// ---------------------------------------------------------------------------
__global__ __launch_bounds__(256, 1) void wn_compute(
    const float* __restrict__ x,   const float* __restrict__ buf,
    const float* __restrict__ inp_w, const float* __restrict__ inp_b,
    const float* __restrict__ fw0, const float* __restrict__ fw1, const float* __restrict__ fb,
    const float* __restrict__ gw0, const float* __restrict__ gw1, const float* __restrict__ gb,
    const float* __restrict__ rw,  const float* __restrict__ rb,
    const float* __restrict__ sw,  const float* __restrict__ sb,
    const float* __restrict__ h1w, const float* __restrict__ h1b,
    const float* __restrict__ h2w, const float* __restrict__ h2b,
    float* __restrict__ out)
{
    extern __shared__ float sm[];
    float* cur = sm;                          // 32*68
    float* zs  = cur + TILE*CURP;             // 32*68 (x tile, then z)
    float* del = zs  + TILE*CURP;             // 10*32*68 taps; head scratch later
    float* w0  = del + NBLK*TILE*CURP;        // 4096 transposed [k][t]
    float* w1  = w0 + 4096;
    float* w2  = w1 + 4096;
    float* w3  = w2 + 4096;
    float* wrs = w3 + 4096;                   // res weights
    float* wst = wrs + 4096;                  // 64*96 skip weights transposed
    float* bia = wst + 6144;                  // fb[64] gb[64] rb[64] sb[96]
    float* ssm = del;                         // head: 32*100 (aliases del)
    float* hsm = del + TILE*SSP;              // head: 32*100

    const int tid   = threadIdx.x;
    const int bbase = blockIdx.x * TILE;
    const int sp = tid >> 4, tg = tid & 15;
    const int s0 = sp*2, s1 = s0+1, t0 = tg*4, ts = tg*6;

    // ---- x tile into zs scratch (32 x 32) ----
    for (int idx = tid; idx < TILE*32; idx += 256)
        zs[idx] = x[(bbase + (idx >> 5))*32 + (idx & 31)];

    // ---- preload all delayed taps: del[i][s][c] = buf[b, c, 2^i - 1] ----
    for (int idx = tid; idx < NBLK*TILE*NCH; idx += 256) {
        int i = idx >> 11;                   // / (32*64)
        int r = idx & 2047;
        int s = r >> 6, c = r & 63;
        int off = (1 << i) - 1;
        del[(i*TILE + s)*CURP + c] =
            buf[((size_t)(bbase + s)*NCH + c)*NCOLS + off];
    }
    __syncthreads();

    // ---- input projection: cur = x @ inp_w.T + inp_b ----
    {
        float a0[4], a1[4];
        #pragma unroll
        for (int j = 0; j < 4; ++j) { a0[j] = inp_b[t0+j]; a1[j] = a0[j]; }
        #pragma unroll 8
        for (int k = 0; k < 32; ++k) {
            float x0 = zs[s0*32+k], x1 = zs[s1*32+k];
            #pragma unroll
            for (int j = 0; j < 4; ++j) {
                float w = inp_w[(t0+j)*32 + k];
                a0[j] += x0*w; a1[j] += x1*w;
            }
        }
        #pragma unroll
        for (int j = 0; j < 4; ++j) {
            cur[s0*CURP + t0 + j] = a0[j];
            cur[s1*CURP + t0 + j] = a1[j];
        }
    }

    float ssum0[6], ssum1[6];
    #pragma unroll
    for (int j = 0; j < 6; ++j) { ssum0[j] = 0.f; ssum1[j] = 0.f; }

    for (int i = 0; i < NBLK; ++i) {
        __syncthreads();   // prev iter done with weights; cur updates visible

        // ---- snapshot current entering block i -> g_currents[i] ----
        {
            float4* dst = (float4*)(g_currents + (size_t)i*NBATCH*NCH
                                               + (size_t)bbase*NCH);
            #pragma unroll
            for (int it = 0; it < 2; ++it) {
                int idx = it*256 + tid;               // 512 float4 = 32*64
                int ss = idx >> 4, q = idx & 15;
                dst[idx] = *(const float4*)(cur + ss*CURP + q*4);
            }
        }

        // ---- stage ALL transposed weights for this block (single phase) ----
        {
            const float* srcs[5] = { fw0 + i*4096, fw1 + i*4096, gw0 + i*4096,
                                     gw1 + i*4096, rw + i*4096 };
            float* dsts[5] = { w0, w1, w2, w3, wrs };
            #pragma unroll
            for (int mm = 0; mm < 5; ++mm) {
                const float* s = srcs[mm]; float* d = dsts[mm];
                #pragma unroll
                for (int it = 0; it < 4; ++it) {
                    int idx = it*256 + tid;           // 1024 float4 total
                    int q = idx >> 6, t = idx & 63;
                    float4 v = *(const float4*)(s + t*64 + q*4);
                    d[(4*q+0)*64+t] = v.x; d[(4*q+1)*64+t] = v.y;
                    d[(4*q+2)*64+t] = v.z; d[(4*q+3)*64+t] = v.w;
                }
            }
            const float* s2 = sw + i*NSKIP*NCH;       // [96][64] -> wst[64][96]
            #pragma unroll
            for (int it = 0; it < 6; ++it) {
                int idx = it*256 + tid;               // 1536 float4 total
                int q = idx / 96, t = idx - q*96;
                float4 v = *(const float4*)(s2 + t*64 + q*4);
                wst[(4*q+0)*96+t] = v.x; wst[(4*q+1)*96+t] = v.y;
                wst[(4*q+2)*96+t] = v.z; wst[(4*q+3)*96+t] = v.w;
            }
            if (tid < 64) {
                bia[tid]      = fb[i*64+tid];
                bia[64+tid]   = gb[i*64+tid];
                bia[128+tid]  = rb[i*64+tid];
            }
            if (tid >= 64 && tid < 160) bia[192+tid-64] = sb[i*NSKIP+tid-64];
        }
        __syncthreads();

        // ---- f/g GEMMs ----
        float f0[4], f1[4], g0[4], g1[4];
        #pragma unroll
        for (int j = 0; j < 4; ++j) {
            f0[j] = bia[t0+j];    f1[j] = f0[j];
            g0[j] = bia[64+t0+j]; g1[j] = g0[j];
        }
        const float* dle = del + i*TILE*CURP;
        #pragma unroll 8
        for (int k = 0; k < 64; ++k) {
            float d0 = dle[s0*CURP+k], d1 = dle[s1*CURP+k];
            float c0 = cur[s0*CURP+k], c1 = cur[s1*CURP+k];
            float4 wa = *(const float4*)(w0 + k*64 + t0);
            float4 wb = *(const float4*)(w1 + k*64 + t0);
            float4 wc = *(const float4*)(w2 + k*64 + t0);
            float4 wd = *(const float4*)(w3 + k*64 + t0);
            FMA4(f0, d0, wa); FMA4(f0, c0, wb);
            FMA4(f1, d1, wa); FMA4(f1, c1, wb);
            FMA4(g0, d0, wc); FMA4(g0, c0, wd);
            FMA4(g1, d1, wc); FMA4(g1, c1, wd);
        }

        // ---- z = tanh(f) * sigmoid(g) ----
        float z0[4], z1[4];
        #pragma unroll
        for (int j = 0; j < 4; ++j) {
            z0[j] = tanhf(f0[j]) * (1.f / (1.f + __expf(-g0[j])));
            z1[j] = tanhf(f1[j]) * (1.f / (1.f + __expf(-g1[j])));
        }
        *(float4*)(zs + s0*CURP + t0) = make_float4(z0[0],z0[1],z0[2],z0[3]);
        *(float4*)(zs + s1*CURP + t0) = make_float4(z1[0],z1[1],z1[2],z1[3]);
        __syncthreads();   // f/g reads of cur done; z visible

        // ---- res + skip GEMMs ----
        float r0[4], r1[4];
        #pragma unroll
        for (int j = 0; j < 4; ++j) { r0[j] = bia[128+t0+j]; r1[j] = r0[j]; }
        #pragma unroll 8
        for (int k = 0; k < 64; ++k) {
            float zk0 = zs[s0*CURP+k], zk1 = zs[s1*CURP+k];
            float4 wv = *(const float4*)(wrs + k*64 + t0);
            FMA4(r0, zk0, wv); FMA4(r1, zk1, wv);
            const float* wsk = wst + k*96 + ts;
            #pragma unroll
            for (int j = 0; j < 6; ++j) {
                float w = wsk[j];
                ssum0[j] += zk0*w; ssum1[j] += zk1*w;
            }
        }
        #pragma unroll
        for (int j = 0; j < 6; ++j) {
            ssum0[j] += bia[192+ts+j];
            ssum1[j] += bia[192+ts+j];
        }

        // ---- residual update of current (owner-exclusive) ----
        {
            float4 c4 = *(float4*)(cur + s0*CURP + t0);
            c4.x += 0.3f*r0[0]; c4.y += 0.3f*r0[1];
            c4.z += 0.3f*r0[2]; c4.w += 0.3f*r0[3];
            *(float4*)(cur + s0*CURP + t0) = c4;
            float4 d4 = *(float4*)(cur + s1*CURP + t0);
            d4.x += 0.3f*r1[0]; d4.y += 0.3f*r1[1];
            d4.z += 0.3f*r1[2]; d4.w += 0.3f*r1[3];
            *(float4*)(cur + s1*CURP + t0) = d4;
        }
    }

    // ---- head (ssm/hsm alias the dead del region) ----
    __syncthreads();
    #pragma unroll
    for (int j = 0; j < 6; ++j) {
        ssm[s0*SSP + ts + j] = fmaxf(ssum0[j], 0.f);
        ssm[s1*SSP + ts + j] = fmaxf(ssum1[j], 0.f);
    }
    for (int idx = tid; idx < NSKIP*NSKIP; idx += 256) {   // h1w transposed
        int k = idx / 96, t = idx - k*96;
        w0[idx] = h1w[t*96 + k];
    }
    __syncthreads();
    {
        float a0[6], a1[6];
        #pragma unroll
        for (int j = 0; j < 6; ++j) { a0[j] = h1b[ts+j]; a1[j] = a0[j]; }
        #pragma unroll 4
        for (int k = 0; k < 96; ++k) {
            float u0 = ssm[s0*SSP+k], u1 = ssm[s1*SSP+k];
            const float* wk = w0 + k*96 + ts;
            #pragma unroll
            for (int j = 0; j < 6; ++j) {
                float w = wk[j];
                a0[j] += u0*w; a1[j] += u1*w;
            }
        }
        #pragma unroll
        for (int j = 0; j < 6; ++j) {
            hsm[s0*SSP + ts + j] = fmaxf(a0[j], 0.f);
            hsm[s1*SSP + ts + j] = fmaxf(a1[j], 0.f);
        }
    }
    __syncthreads();
    if (tid < 64) {
        int s = tid >> 1, jj = tid & 1;
        float a = h2b[jj];
        #pragma unroll 4
        for (int k = 0; k < 96; ++k)
            a += hsm[s*SSP+k] * h2w[jj*96+k];
        out[(bbase+s)*2 + jj] = a;
    }
}

// ---------------------------------------------------------------------------
// Shift: dst[n] = src[n+1], fully coalesced (lane-interleaved float4).
// Warp owns 2048 contiguous floats: A[r] = f4[r*32 + lane], r = 0..15.
// Grid 16368 x 128 covers NBUF exactly (16368*8192 = 134086656).
// ---------------------------------------------------------------------------
__global__ __launch_bounds__(128) void wn_shift(const float* __restrict__ src,
                                                float* __restrict__ dst)
{
    const int warp = threadIdx.x >> 5;
    const unsigned lane = threadIdx.x & 31;
    const size_t base = (size_t)blockIdx.x*8192 + (size_t)warp*2048;  // floats
    const float4* s4 = (const float4*)(src + base);
    float4*       d4 = (float4*)(dst + base);

    float bnd = 0.f;
    if (lane == 31) {
        size_t g = base + 2048;
        bnd = src[g < NBUF ? g : NBUF - 1];   // clamp slot is an insertion col
    }
    float4 A[16];
    #pragma unroll
    for (int r = 0; r < 16; ++r) A[r] = s4[r*32 + lane];

    #pragma unroll
    for (int r = 0; r < 16; ++r) {
        float nd = __shfl_down_sync(0xffffffffu, A[r].x, 1);
        float n0 = (r < 15) ? __shfl_sync(0xffffffffu, A[r+1].x, 0) : bnd;
        float nxt = (lane == 31) ? n0 : nd;
        d4[r*32 + lane] = make_float4(A[r].y, A[r].z, A[r].w, nxt);
    }
}

// ---------------------------------------------------------------------------
// Scatter: overwrite the 10 insertion columns j = 2^(i+1)-2 with current_i.
// ---------------------------------------------------------------------------
__global__ __launch_bounds__(256) void wn_scatter(float* __restrict__ dst)
{
    int idx = blockIdx.x*blockDim.x + threadIdx.x;
    if (idx < NBLK*NBATCH*NCH) {
        int i = idx >> 17;                 // / (2048*64)
        int r = idx & ((1 << 17) - 1);     // b*64+c
        int j = (2 << i) - 2;              // 2^(i+1)-2
        dst[(size_t)r*NCOLS + j] = g_currents[idx];
    }
}

extern "C" void kernel_launch(void* const* d_in, const int* in_sizes, int n_in,
                              void* d_out, int out_size)
{
    const float* x     = (const float*)d_in[0];
    const float* buf   = (const float*)d_in[1];
    const float* inp_w = (const float*)d_in[2];
    const float* inp_b = (const float*)d_in[3];
    const float* fw0   = (const float*)d_in[4];
    const float* fw1   = (const float*)d_in[5];
    const float* fb    = (const float*)d_in[6];
    const float* gw0   = (const float*)d_in[7];
    const float* gw1   = (const float*)d_in[8];
    const float* gb    = (const float*)d_in[9];
    const float* rw    = (const float*)d_in[10];
    const float* rb    = (const float*)d_in[11];
    const float* sw    = (const float*)d_in[12];
    const float* sb    = (const float*)d_in[13];
    const float* h1w   = (const float*)d_in[14];
    const float* h1b   = (const float*)d_in[15];
    const float* h2w   = (const float*)d_in[16];
    const float* h2b   = (const float*)d_in[17];

    float* out  = (float*)d_out;            // (2048, 2)
    float* nbuf = out + NBATCH*2;           // (2048, 64, 1023)

    // lazy one-time creation (first call = correctness run, before capture)
    static cudaStream_t s2 = nullptr;
    static cudaEvent_t ev_fork = nullptr, ev_join = nullptr;
    if (!s2) {
        int lo, hi;
        cudaDeviceGetStreamPriorityRange(&lo, &hi);   // lo = LEAST priority
        cudaStreamCreateWithPriority(&s2, cudaStreamNonBlocking, lo);
        cudaEventCreateWithFlags(&ev_fork, cudaEventDisableTiming);
        cudaEventCreateWithFlags(&ev_join, cudaEventDisableTiming);
    }

    const int smem_bytes =
        (TILE*CURP*2 + NBLK*TILE*CURP + 5*4096 + 6144 + 288)
        * (int)sizeof(float);               // 212,096 B
    cudaFuncSetAttribute(wn_compute, cudaFuncAttributeMaxDynamicSharedMemorySize,
                         smem_bytes);

    // fork: compute launched FIRST (grabs its SM slots); shift fills the rest
    cudaEventRecord(ev_fork, 0);
    cudaStreamWaitEvent(s2, ev_fork, 0);

    wn_compute<<<NCTA, 256, smem_bytes>>>(
        x, buf, inp_w, inp_b, fw0, fw1, fb, gw0, gw1, gb,
        rw, rb, sw, sb, h1w, h1b, h2w, h2b, out);

    wn_shift<<<16368, 128, 0, s2>>>(buf, nbuf);
    cudaEventRecord(ev_join, s2);

    // join: scatter needs both compute (g_currents) and shift (nbuf)
    cudaStreamWaitEvent(0, ev_join, 0);
    wn_scatter<<<(NBLK*NBATCH*NCH)/256, 256>>>(nbuf);
}

// round 10
// speedup vs baseline: 1.3852x; 1.3852x over previous
#include <cuda_runtime.h>

#define NBLK   10
#define NBATCH 2048
#define NCH    64
#define NSKIP  96
#define TILE   16
#define NCOLS  1023
#define CURP   68                      /* padded row stride for cur/del/z */
#define SSP    100                     /* padded row stride for skip/h */
#define NBUF   ((size_t)NBATCH*NCH*NCOLS)   /* 134086656 */

__device__ float g_currents[NBLK * NBATCH * NCH];

#define FMA2(acc, s, v) do { (acc)[0] += (s)*(v).x; (acc)[1] += (s)*(v).y; } while(0)

// ---------------------------------------------------------------------------
// Compute kernel: 128 CTAs x 256 threads. CTA owns 16 samples (128 SMs busy).
// Thread = (sp 0..7 = warp, lane 0..31): 2 samples x 2 channels.
// Per-warp instruction count is HALF of the R1 layout; 2 warps/SMSP.
// Activation smem reads are single-address warp broadcasts.
// ---------------------------------------------------------------------------
__global__ __launch_bounds__(256, 1) void wn_compute(
    const float* __restrict__ x,   const float* __restrict__ buf,
    const float* __restrict__ inp_w, const float* __restrict__ inp_b,
    const float* __restrict__ fw0, const float* __restrict__ fw1, const float* __restrict__ fb,
    const float* __restrict__ gw0, const float* __restrict__ gw1, const float* __restrict__ gb,
    const float* __restrict__ rw,  const float* __restrict__ rb,
    const float* __restrict__ sw,  const float* __restrict__ sb,
    const float* __restrict__ h1w, const float* __restrict__ h1b,
    const float* __restrict__ h2w, const float* __restrict__ h2b,
    float* __restrict__ out)
{
    extern __shared__ float sm[];
    float* cur = sm;                          // 16*68
    float* del = cur + TILE*CURP;             // 10*16*68
    float* zs  = del + NBLK*TILE*CURP;        // 16*68
    float* w0  = zs  + TILE*CURP;             // 4096  (transposed [k][t], row 64)
    float* w1  = w0 + 4096;
    float* w2  = w1 + 4096;
    float* w3  = w2 + 4096;
    float* wrs = w3 + 4096;                   // res weights
    float* wst = wrs + 4096;                  // 64*96 skip weights transposed
    float* bia = wst + 6144;                  // fb[64] gb[64] rb[64] sb[96]
    float* ssm = bia + 288;                   // 16*100 skip sums
    float* hsm = ssm + TILE*SSP;              // 16*100 hidden

    const int tid  = threadIdx.x;
    const int lane = tid & 31;
    const int sp   = tid >> 5;                // warp id = sample pair
    const int s0 = sp*2, s1 = s0+1;
    const int t0 = lane*2;                    // 2 channels
    const int ts = lane*3;                    // 3 skip outputs
    const int bbase = blockIdx.x * TILE;

    // ---- x tile into zs scratch (16 x 32) ----
    for (int idx = tid; idx < TILE*32; idx += 256)
        zs[idx] = x[(bbase + (idx >> 5))*32 + (idx & 31)];
    __syncthreads();

    // ---- input projection: cur = x @ inp_w.T + inp_b (2 samp x 2 ch) ----
    {
        float a0[2], a1[2];
        #pragma unroll
        for (int j = 0; j < 2; ++j) { a0[j] = inp_b[t0+j]; a1[j] = a0[j]; }
        #pragma unroll 8
        for (int k = 0; k < 32; ++k) {
            float x0 = zs[s0*32+k], x1 = zs[s1*32+k];
            #pragma unroll
            for (int j = 0; j < 2; ++j) {
                float w = inp_w[(t0+j)*32 + k];
                a0[j] += x0*w; a1[j] += x1*w;
            }
        }
        #pragma unroll
        for (int j = 0; j < 2; ++j) {
            cur[s0*CURP + t0 + j] = a0[j];
            cur[s1*CURP + t0 + j] = a1[j];
        }
    }

    // ---- preload all delayed taps: del[i][s][c] = buf[b, c, 2^i - 1] ----
    for (int idx = tid; idx < NBLK*TILE*NCH; idx += 256) {
        int i = idx >> 10;
        int r = idx & 1023;
        int s = r >> 6, c = r & 63;
        int off = (1 << i) - 1;
        del[(i*TILE + s)*CURP + c] =
            buf[((size_t)(bbase+s)*NCH + c)*NCOLS + off];
    }

    float ssum0[3], ssum1[3];
    #pragma unroll
    for (int j = 0; j < 3; ++j) { ssum0[j] = 0.f; ssum1[j] = 0.f; }

    for (int i = 0; i < NBLK; ++i) {
        __syncthreads();

        // ---- snapshot current entering block i -> g_currents[i] ----
        {
            float4* dst = (float4*)(g_currents + (size_t)i*NBATCH*NCH
                                               + (size_t)bbase*NCH);
            for (int idx = tid; idx < TILE*NCH/4; idx += 256) {
                int s = idx >> 4, q = idx & 15;
                dst[idx] = *(const float4*)(cur + s*CURP + q*4);
            }
        }

        // ---- stage transposed weights for this block ----
        {
            const float* srcs[5] = { fw0 + i*4096, fw1 + i*4096, gw0 + i*4096,
                                     gw1 + i*4096, rw + i*4096 };
            float* dsts[5] = { w0, w1, w2, w3, wrs };
            #pragma unroll
            for (int mm = 0; mm < 5; ++mm) {
                const float* s = srcs[mm]; float* d = dsts[mm];
                #pragma unroll
                for (int it = 0; it < 4; ++it) {
                    int idx = it*256 + tid;           // 1024 float4 total
                    int q = idx >> 6, t = idx & 63;
                    float4 v = *(const float4*)(s + t*64 + q*4);
                    d[(4*q+0)*64+t] = v.x; d[(4*q+1)*64+t] = v.y;
                    d[(4*q+2)*64+t] = v.z; d[(4*q+3)*64+t] = v.w;
                }
            }
            const float* s2 = sw + i*NSKIP*NCH;       // [96][64] -> wst[64][96]
            #pragma unroll
            for (int it = 0; it < 6; ++it) {
                int idx = it*256 + tid;               // 1536 float4 total
                int q = idx / 96, t = idx - q*96;
                float4 v = *(const float4*)(s2 + t*64 + q*4);
                wst[(4*q+0)*96+t] = v.x; wst[(4*q+1)*96+t] = v.y;
                wst[(4*q+2)*96+t] = v.z; wst[(4*q+3)*96+t] = v.w;
            }
            if (tid < 64) {
                bia[tid]      = fb[i*64+tid];
                bia[64+tid]   = gb[i*64+tid];
                bia[128+tid]  = rb[i*64+tid];
            }
            if (tid >= 64 && tid < 160) bia[192+tid-64] = sb[i*NSKIP+tid-64];
        }
        __syncthreads();

        // ---- f/g GEMMs (2 samp x 2 ch) ----
        float f0[2], f1[2], g0[2], g1[2];
        #pragma unroll
        for (int j = 0; j < 2; ++j) {
            f0[j] = bia[t0+j];    f1[j] = f0[j];
            g0[j] = bia[64+t0+j]; g1[j] = g0[j];
        }
        const float* dle = del + i*TILE*CURP;
        #pragma unroll 8
        for (int k = 0; k < 64; ++k) {
            float d0 = dle[s0*CURP+k], d1 = dle[s1*CURP+k];
            float c0 = cur[s0*CURP+k], c1 = cur[s1*CURP+k];
            float2 wa = *(const float2*)(w0 + k*64 + t0);
            float2 wb = *(const float2*)(w1 + k*64 + t0);
            float2 wc = *(const float2*)(w2 + k*64 + t0);
            float2 wd = *(const float2*)(w3 + k*64 + t0);
            FMA2(f0, d0, wa); FMA2(f0, c0, wb);
            FMA2(f1, d1, wa); FMA2(f1, c1, wb);
            FMA2(g0, d0, wc); FMA2(g0, c0, wd);
            FMA2(g1, d1, wc); FMA2(g1, c1, wd);
        }

        // ---- z = tanh(f) * sigmoid(g) ----
        float z0[2], z1[2];
        #pragma unroll
        for (int j = 0; j < 2; ++j) {
            z0[j] = tanhf(f0[j]) * (1.f / (1.f + __expf(-g0[j])));
            z1[j] = tanhf(f1[j]) * (1.f / (1.f + __expf(-g1[j])));
        }
        *(float2*)(zs + s0*CURP + t0) = make_float2(z0[0], z0[1]);
        *(float2*)(zs + s1*CURP + t0) = make_float2(z1[0], z1[1]);
        __syncthreads();

        // ---- res + skip GEMMs ----
        float r0[2], r1[2];
        #pragma unroll
        for (int j = 0; j < 2; ++j) { r0[j] = bia[128+t0+j]; r1[j] = r0[j]; }
        #pragma unroll 8
        for (int k = 0; k < 64; ++k) {
            float zk0 = zs[s0*CURP+k], zk1 = zs[s1*CURP+k];
            float2 wv = *(const float2*)(wrs + k*64 + t0);
            FMA2(r0, zk0, wv); FMA2(r1, zk1, wv);
            const float* wsk = wst + k*96 + ts;
            #pragma unroll
            for (int j = 0; j < 3; ++j) {
                float w = wsk[j];
                ssum0[j] += zk0*w; ssum1[j] += zk1*w;
            }
        }
        #pragma unroll
        for (int j = 0; j < 3; ++j) {
            ssum0[j] += bia[192+ts+j];
            ssum1[j] += bia[192+ts+j];
        }

        // ---- residual update of current (owner-exclusive) ----
        {
            float2 c2 = *(float2*)(cur + s0*CURP + t0);
            c2.x += 0.3f*r0[0]; c2.y += 0.3f*r0[1];
            *(float2*)(cur + s0*CURP + t0) = c2;
            float2 d2 = *(float2*)(cur + s1*CURP + t0);
            d2.x += 0.3f*r1[0]; d2.y += 0.3f*r1[1];
            *(float2*)(cur + s1*CURP + t0) = d2;
        }
    }

    // ---- head ----
    __syncthreads();
    #pragma unroll
    for (int j = 0; j < 3; ++j) {
        ssm[s0*SSP + ts + j] = fmaxf(ssum0[j], 0.f);
        ssm[s1*SSP + ts + j] = fmaxf(ssum1[j], 0.f);
    }
    float* h1T = w0;                              // 9216 floats
    for (int idx = tid; idx < NSKIP*NSKIP; idx += 256) {
        int k = idx / 96, t = idx - k*96;
        h1T[idx] = h1w[t*96 + k];
    }
    __syncthreads();
    {
        float a0[3], a1[3];
        #pragma unroll
        for (int j = 0; j < 3; ++j) { a0[j] = h1b[ts+j]; a1[j] = a0[j]; }
        #pragma unroll 4
        for (int k = 0; k < 96; ++k) {
            float u0 = ssm[s0*SSP+k], u1 = ssm[s1*SSP+k];
            const float* wk = h1T + k*96 + ts;
            #pragma unroll
            for (int j = 0; j < 3; ++j) {
                float w = wk[j];
                a0[j] += u0*w; a1[j] += u1*w;
            }
        }
        #pragma unroll
        for (int j = 0; j < 3; ++j) {
            hsm[s0*SSP + ts + j] = fmaxf(a0[j], 0.f);
            hsm[s1*SSP + ts + j] = fmaxf(a1[j], 0.f);
        }
    }
    __syncthreads();
    if (tid < 32) {
        int s = tid >> 1, jj = tid & 1;
        float a = h2b[jj];
        #pragma unroll 4
        for (int k = 0; k < 96; ++k)
            a += hsm[s*SSP+k] * h2w[jj*96+k];
        out[(bbase+s)*2 + jj] = a;
    }
}

// ---------------------------------------------------------------------------
// Shift: dst[n] = src[n+1], fully coalesced (lane-interleaved float4).
// Warp owns 2048 contiguous floats: A[r] = f4[r*32 + lane], r = 0..15.
// Grid 16368 x 128 covers NBUF exactly (16368*8192 = 134086656).
// ---------------------------------------------------------------------------
__global__ __launch_bounds__(128) void wn_shift(const float* __restrict__ src,
                                                float* __restrict__ dst)
{
    const int warp = threadIdx.x >> 5;
    const unsigned lane = threadIdx.x & 31;
    const size_t base = (size_t)blockIdx.x*8192 + (size_t)warp*2048;  // floats
    const float4* s4 = (const float4*)(src + base);
    float4*       d4 = (float4*)(dst + base);

    float bnd = 0.f;
    if (lane == 31) {
        size_t g = base + 2048;
        bnd = src[g < NBUF ? g : NBUF - 1];   // clamp slot is an insertion col
    }
    float4 A[16];
    #pragma unroll
    for (int r = 0; r < 16; ++r) A[r] = s4[r*32 + lane];

    #pragma unroll
    for (int r = 0; r < 16; ++r) {
        float nd = __shfl_down_sync(0xffffffffu, A[r].x, 1);
        float n0 = (r < 15) ? __shfl_sync(0xffffffffu, A[r+1].x, 0) : bnd;
        float nxt = (lane == 31) ? n0 : nd;
        d4[r*32 + lane] = make_float4(A[r].y, A[r].z, A[r].w, nxt);
    }
}

// ---------------------------------------------------------------------------
// Scatter: overwrite the 10 insertion columns j = 2^(i+1)-2 with current_i.
// ---------------------------------------------------------------------------
__global__ __launch_bounds__(256) void wn_scatter(float* __restrict__ dst)
{
    int idx = blockIdx.x*blockDim.x + threadIdx.x;
    if (idx < NBLK*NBATCH*NCH) {
        int i = idx >> 17;                 // / (2048*64)
        int r = idx & ((1 << 17) - 1);     // b*64+c
        int j = (2 << i) - 2;              // 2^(i+1)-2
        dst[(size_t)r*NCOLS + j] = g_currents[idx];
    }
}

extern "C" void kernel_launch(void* const* d_in, const int* in_sizes, int n_in,
                              void* d_out, int out_size)
{
    const float* x     = (const float*)d_in[0];
    const float* buf   = (const float*)d_in[1];
    const float* inp_w = (const float*)d_in[2];
    const float* inp_b = (const float*)d_in[3];
    const float* fw0   = (const float*)d_in[4];
    const float* fw1   = (const float*)d_in[5];
    const float* fb    = (const float*)d_in[6];
    const float* gw0   = (const float*)d_in[7];
    const float* gw1   = (const float*)d_in[8];
    const float* gb    = (const float*)d_in[9];
    const float* rw    = (const float*)d_in[10];
    const float* rb    = (const float*)d_in[11];
    const float* sw    = (const float*)d_in[12];
    const float* sb    = (const float*)d_in[13];
    const float* h1w   = (const float*)d_in[14];
    const float* h1b   = (const float*)d_in[15];
    const float* h2w   = (const float*)d_in[16];
    const float* h2b   = (const float*)d_in[17];

    float* out  = (float*)d_out;            // (2048, 2)
    float* nbuf = out + NBATCH*2;           // (2048, 64, 1023)

    // lazy one-time creation (first call = correctness run, before capture)
    static cudaStream_t s2 = nullptr;
    static cudaEvent_t ev_fork = nullptr, ev_join = nullptr;
    if (!s2) {
        int lo, hi;
        cudaDeviceGetStreamPriorityRange(&lo, &hi);   // lo = LEAST priority
        cudaStreamCreateWithPriority(&s2, cudaStreamNonBlocking, lo);
        cudaEventCreateWithFlags(&ev_fork, cudaEventDisableTiming);
        cudaEventCreateWithFlags(&ev_join, cudaEventDisableTiming);
    }

    const int smem_bytes = (TILE*CURP*(NBLK+2) + 5*4096 + 6144 + 288 + 2*TILE*SSP)
                           * (int)sizeof(float);     // 172672 B (as R1/R7)
    cudaFuncSetAttribute(wn_compute, cudaFuncAttributeMaxDynamicSharedMemorySize,
                         smem_bytes);

    // fork: compute launched FIRST (grabs its SM slots); shift fills the rest
    cudaEventRecord(ev_fork, 0);
    cudaStreamWaitEvent(s2, ev_fork, 0);

    wn_compute<<<NBATCH/TILE, 256, smem_bytes>>>(
        x, buf, inp_w, inp_b, fw0, fw1, fb, gw0, gw1, gb,
        rw, rb, sw, sb, h1w, h1b, h2w, h2b, out);

    wn_shift<<<16368, 128, 0, s2>>>(buf, nbuf);
    cudaEventRecord(ev_join, s2);

    // join: scatter needs both compute (g_currents) and shift (nbuf)
    cudaStreamWaitEvent(0, ev_join, 0);
    wn_scatter<<<(NBLK*NBATCH*NCH)/256, 256>>>(nbuf);
}

// round 11
// speedup vs baseline: 1.6962x; 1.2245x over previous
#include <cuda_runtime.h>

#define NBLK   10
#define NBATCH 2048
#define NCH    64
#define NSKIP  96
#define TILE   16
#define NCOLS  1023
#define CURP   68                      /* padded row stride for cur/del/z */
#define SSP    100                     /* padded row stride for skip/h */
#define NBUF   ((size_t)NBATCH*NCH*NCOLS)   /* 134086656 */

typedef unsigned long long u64;

__device__ __forceinline__ u64 pk2(float a, float b) {
    u64 r; asm("mov.b64 %0, {%1, %2};" : "=l"(r) : "f"(a), "f"(b)); return r;
}
__device__ __forceinline__ u64 dup2(float a) {
    u64 r; asm("mov.b64 %0, {%1, %1};" : "=l"(r) : "f"(a)); return r;
}
__device__ __forceinline__ u64 fma2p(u64 a, u64 b, u64 c) {
    u64 d; asm("fma.rn.f32x2 %0, %1, %2, %3;" : "=l"(d) : "l"(a), "l"(b), "l"(c));
    return d;
}
__device__ __forceinline__ u64 add2p(u64 a, u64 b) {
    u64 d; asm("add.rn.f32x2 %0, %1, %2;" : "=l"(d) : "l"(a), "l"(b)); return d;
}
__device__ __forceinline__ void up2(u64 v, float& a, float& b) {
    asm("mov.b64 {%0, %1}, %2;" : "=f"(a), "=f"(b) : "l"(v));
}

// ---------------------------------------------------------------------------
// Compute kernel: 128 CTAs x 128 threads (proven R1 shape) with packed
// f32x2 FMAs (SASS FFMA2) — halves FMA instruction count, bit-identical math.
// Per-block "current" snapshots are written DIRECTLY to nbuf insertion cols.
// ---------------------------------------------------------------------------
__global__ __launch_bounds__(128, 1) void wn_compute(
    const float* __restrict__ x,   const float* __restrict__ buf,
    const float* __restrict__ inp_w, const float* __restrict__ inp_b,
    const float* __restrict__ fw0, const float* __restrict__ fw1, const float* __restrict__ fb,
    const float* __restrict__ gw0, const float* __restrict__ gw1, const float* __restrict__ gb,
    const float* __restrict__ rw,  const float* __restrict__ rb,
    const float* __restrict__ sw,  const float* __restrict__ sb,
    const float* __restrict__ h1w, const float* __restrict__ h1b,
    const float* __restrict__ h2w, const float* __restrict__ h2b,
    float* __restrict__ out, float* __restrict__ nbuf)
{
    extern __shared__ float sm[];
    float* cur = sm;                          // 16*68
    float* del = cur + TILE*CURP;             // 10*16*68
    float* zs  = del + NBLK*TILE*CURP;        // 16*68
    float* w0  = zs  + TILE*CURP;             // 4096  (transposed [k][t], row 64)
    float* w1  = w0 + 4096;
    float* w2  = w1 + 4096;
    float* w3  = w2 + 4096;
    float* wrs = w3 + 4096;                   // res weights
    float* wst = wrs + 4096;                  // 64*96 skip weights transposed
    float* bia = wst + 6144;                  // fb[64] gb[64] rb[64] sb[96]
    float* ssm = bia + 288;                   // 16*100 skip sums
    float* hsm = ssm + TILE*SSP;              // 16*100 hidden

    const int tid  = threadIdx.x;
    const int lane = tid & 31, warp = tid >> 5;
    const int sp = tid >> 4, tg = tid & 15;
    const int s0 = sp*2, s1 = s0+1, t0 = tg*4;
    const int bbase = blockIdx.x * TILE;

    // ---- x tile into zs scratch (16 x 32) ----
    for (int idx = tid; idx < TILE*32; idx += 128) {
        int s = idx >> 5, k = idx & 31;
        zs[idx] = x[(bbase+s)*32 + k];
    }
    __syncthreads();

    // ---- input projection: cur = x @ inp_w.T + inp_b ----
    {
        float a0[4], a1[4];
        #pragma unroll
        for (int j = 0; j < 4; ++j) { a0[j] = inp_b[t0+j]; a1[j] = a0[j]; }
        #pragma unroll 8
        for (int k = 0; k < 32; ++k) {
            float x0 = zs[s0*32+k], x1 = zs[s1*32+k];
            #pragma unroll
            for (int j = 0; j < 4; ++j) {
                float w = inp_w[(t0+j)*32 + k];
                a0[j] += x0*w; a1[j] += x1*w;
            }
        }
        #pragma unroll
        for (int j = 0; j < 4; ++j) {
            cur[s0*CURP + t0 + j] = a0[j];
            cur[s1*CURP + t0 + j] = a1[j];
        }
    }

    // ---- preload all delayed taps: del[i][s][c] = buf[b, c, 2^i - 1] ----
    for (int idx = tid; idx < NBLK*TILE*NCH; idx += 128) {
        int i = idx >> 10;
        int r = idx & 1023;
        int s = r >> 6, c = r & 63;
        int off = (1 << i) - 1;
        del[(i*TILE + s)*CURP + c] =
            buf[((size_t)(bbase+s)*NCH + c)*NCOLS + off];
    }

    u64 sa0 = 0ull, sa1 = 0ull, sa2 = 0ull;   // skip sums sample s0 (3 ch-pairs)
    u64 sb0 = 0ull, sb1 = 0ull, sb2 = 0ull;   // sample s1
    const int ts = tg*6;

    for (int i = 0; i < NBLK; ++i) {
        __syncthreads();

        // ---- write current entering block i DIRECTLY to nbuf insertion col
        {
            int jcol = (2 << i) - 2;                  // 2^(i+1)-2
            for (int idx = tid; idx < TILE*NCH; idx += 128) {
                int s = idx >> 6, c = idx & 63;
                nbuf[((size_t)(bbase+s)*NCH + c)*NCOLS + jcol] = cur[s*CURP + c];
            }
        }

        // ---- stage transposed weights for this block ----
        {
            const float* srcs[5] = { fw0 + i*4096, fw1 + i*4096, gw0 + i*4096,
                                     gw1 + i*4096, rw + i*4096 };
            float* dsts[5] = { w0, w1, w2, w3, wrs };
            #pragma unroll
            for (int mm = 0; mm < 5; ++mm) {
                const float* s = srcs[mm]; float* d = dsts[mm];
                #pragma unroll
                for (int th = 0; th < 2; ++th) {
                    int t = th*32 + lane;
                    #pragma unroll
                    for (int kc = 0; kc < 4; ++kc) {
                        int k0 = warp*16 + kc*4;
                        float4 v = *(const float4*)(s + t*64 + k0);
                        d[(k0+0)*64+t] = v.x; d[(k0+1)*64+t] = v.y;
                        d[(k0+2)*64+t] = v.z; d[(k0+3)*64+t] = v.w;
                    }
                }
            }
            const float* s = sw + i*NSKIP*NCH;   // [96][64] -> wst[64][96]
            #pragma unroll
            for (int th = 0; th < 3; ++th) {
                int t = th*32 + lane;
                #pragma unroll
                for (int kc = 0; kc < 4; ++kc) {
                    int k0 = warp*16 + kc*4;
                    float4 v = *(const float4*)(s + t*64 + k0);
                    wst[(k0+0)*96+t] = v.x; wst[(k0+1)*96+t] = v.y;
                    wst[(k0+2)*96+t] = v.z; wst[(k0+3)*96+t] = v.w;
                }
            }
            if (tid < 64) {
                bia[tid]      = fb[i*64+tid];
                bia[64+tid]   = gb[i*64+tid];
                bia[128+tid]  = rb[i*64+tid];
            }
            if (tid < 96) bia[192+tid] = sb[i*NSKIP+tid];
        }
        __syncthreads();

        // ---- f/g GEMMs (packed f32x2) ----
        u64 f0a = pk2(bia[t0],   bia[t0+1]),   f0b = pk2(bia[t0+2],   bia[t0+3]);
        u64 f1a = f0a, f1b = f0b;
        u64 g0a = pk2(bia[64+t0],bia[64+t0+1]),g0b = pk2(bia[64+t0+2],bia[64+t0+3]);
        u64 g1a = g0a, g1b = g0b;
        const float* dle = del + i*TILE*CURP;
        #pragma unroll 8
        for (int k = 0; k < 64; ++k) {
            u64 D0 = dup2(dle[s0*CURP+k]), D1 = dup2(dle[s1*CURP+k]);
            u64 C0 = dup2(cur[s0*CURP+k]), C1 = dup2(cur[s1*CURP+k]);
            ulonglong2 wa = *(const ulonglong2*)(w0 + k*64 + t0);
            ulonglong2 wb = *(const ulonglong2*)(w1 + k*64 + t0);
            ulonglong2 wc = *(const ulonglong2*)(w2 + k*64 + t0);
            ulonglong2 wd = *(const ulonglong2*)(w3 + k*64 + t0);
            f0a = fma2p(D0, wa.x, f0a); f0b = fma2p(D0, wa.y, f0b);
            f0a = fma2p(C0, wb.x, f0a); f0b = fma2p(C0, wb.y, f0b);
            f1a = fma2p(D1, wa.x, f1a); f1b = fma2p(D1, wa.y, f1b);
            f1a = fma2p(C1, wb.x, f1a); f1b = fma2p(C1, wb.y, f1b);
            g0a = fma2p(D0, wc.x, g0a); g0b = fma2p(D0, wc.y, g0b);
            g0a = fma2p(C0, wd.x, g0a); g0b = fma2p(C0, wd.y, g0b);
            g1a = fma2p(D1, wc.x, g1a); g1b = fma2p(D1, wc.y, g1b);
            g1a = fma2p(C1, wd.x, g1a); g1b = fma2p(C1, wd.y, g1b);
        }
        float f0[4], f1[4], g0[4], g1[4];
        up2(f0a, f0[0], f0[1]); up2(f0b, f0[2], f0[3]);
        up2(f1a, f1[0], f1[1]); up2(f1b, f1[2], f1[3]);
        up2(g0a, g0[0], g0[1]); up2(g0b, g0[2], g0[3]);
        up2(g1a, g1[0], g1[1]); up2(g1b, g1[2], g1[3]);

        // ---- z = tanh(f) * sigmoid(g) ----
        float z0[4], z1[4];
        #pragma unroll
        for (int j = 0; j < 4; ++j) {
            z0[j] = tanhf(f0[j]) * (1.f / (1.f + __expf(-g0[j])));
            z1[j] = tanhf(f1[j]) * (1.f / (1.f + __expf(-g1[j])));
        }
        *(float4*)(zs + s0*CURP + t0) = make_float4(z0[0],z0[1],z0[2],z0[3]);
        *(float4*)(zs + s1*CURP + t0) = make_float4(z1[0],z1[1],z1[2],z1[3]);
        __syncthreads();

        // ---- res + skip GEMMs (packed f32x2) ----
        u64 r0a = pk2(bia[128+t0],   bia[128+t0+1]);
        u64 r0b = pk2(bia[128+t0+2], bia[128+t0+3]);
        u64 r1a = r0a, r1b = r0b;
        #pragma unroll 8
        for (int k = 0; k < 64; ++k) {
            u64 Z0 = dup2(zs[s0*CURP+k]), Z1 = dup2(zs[s1*CURP+k]);
            ulonglong2 wv = *(const ulonglong2*)(wrs + k*64 + t0);
            r0a = fma2p(Z0, wv.x, r0a); r0b = fma2p(Z0, wv.y, r0b);
            r1a = fma2p(Z1, wv.x, r1a); r1b = fma2p(Z1, wv.y, r1b);
            const u64* wsk = (const u64*)(wst + k*96 + ts);
            u64 wk0 = wsk[0], wk1 = wsk[1], wk2 = wsk[2];
            sa0 = fma2p(Z0, wk0, sa0); sa1 = fma2p(Z0, wk1, sa1);
            sa2 = fma2p(Z0, wk2, sa2);
            sb0 = fma2p(Z1, wk0, sb0); sb1 = fma2p(Z1, wk1, sb1);
            sb2 = fma2p(Z1, wk2, sb2);
        }
        {   // skip biases for this block
            const u64* bb = (const u64*)(bia + 192 + ts);
            u64 b0 = bb[0], b1 = bb[1], b2 = bb[2];
            sa0 = add2p(sa0, b0); sa1 = add2p(sa1, b1); sa2 = add2p(sa2, b2);
            sb0 = add2p(sb0, b0); sb1 = add2p(sb1, b1); sb2 = add2p(sb2, b2);
        }

        // ---- residual update of current (owner-exclusive) ----
        {
            float r0[4], r1[4];
            up2(r0a, r0[0], r0[1]); up2(r0b, r0[2], r0[3]);
            up2(r1a, r1[0], r1[1]); up2(r1b, r1[2], r1[3]);
            float4 c4 = *(float4*)(cur + s0*CURP + t0);
            c4.x += 0.3f*r0[0]; c4.y += 0.3f*r0[1];
            c4.z += 0.3f*r0[2]; c4.w += 0.3f*r0[3];
            *(float4*)(cur + s0*CURP + t0) = c4;
            float4 d4 = *(float4*)(cur + s1*CURP + t0);
            d4.x += 0.3f*r1[0]; d4.y += 0.3f*r1[1];
            d4.z += 0.3f*r1[2]; d4.w += 0.3f*r1[3];
            *(float4*)(cur + s1*CURP + t0) = d4;
        }
    }

    // ---- head ----
    __syncthreads();
    {
        float ssum0[6], ssum1[6];
        up2(sa0, ssum0[0], ssum0[1]); up2(sa1, ssum0[2], ssum0[3]);
        up2(sa2, ssum0[4], ssum0[5]);
        up2(sb0, ssum1[0], ssum1[1]); up2(sb1, ssum1[2], ssum1[3]);
        up2(sb2, ssum1[4], ssum1[5]);
        #pragma unroll
        for (int j = 0; j < 6; ++j) {
            ssm[s0*SSP + ts + j] = fmaxf(ssum0[j], 0.f);
            ssm[s1*SSP + ts + j] = fmaxf(ssum1[j], 0.f);
        }
    }
    float* h1T = w0;
    for (int idx = tid; idx < NSKIP*NSKIP; idx += 128) {
        int k = idx / 96, t = idx - k*96;
        h1T[idx] = h1w[t*96 + k];
    }
    __syncthreads();
    {
        float a0[6], a1[6];
        #pragma unroll
        for (int j = 0; j < 6; ++j) { a0[j] = h1b[ts+j]; a1[j] = a0[j]; }
        #pragma unroll 4
        for (int k = 0; k < 96; ++k) {
            float u0 = ssm[s0*SSP+k], u1 = ssm[s1*SSP+k];
            const float* wk = h1T + k*96 + ts;
            #pragma unroll
            for (int j = 0; j < 6; ++j) {
                float w = wk[j];
                a0[j] += u0*w; a1[j] += u1*w;
            }
        }
        #pragma unroll
        for (int j = 0; j < 6; ++j) {
            hsm[s0*SSP + ts + j] = fmaxf(a0[j], 0.f);
            hsm[s1*SSP + ts + j] = fmaxf(a1[j], 0.f);
        }
    }
    __syncthreads();
    if (tid < 32) {
        int s = tid >> 1, jj = tid & 1;
        float a = h2b[jj];
        #pragma unroll 4
        for (int k = 0; k < 96; ++k)
            a += hsm[s*SSP+k] * h2w[jj*96+k];
        out[(bbase+s)*2 + jj] = a;
    }
}

// ---------------------------------------------------------------------------
// Shift: dst[n] = src[n+1], fully coalesced, SKIPPING the 10 insertion
// columns per row (col+2 is a power of two <=1024 <=> insertion col).
// Those are written by wn_compute directly — no scatter kernel, no race.
// Grid 16368 x 128 covers NBUF exactly.
// ---------------------------------------------------------------------------
__global__ __launch_bounds__(128) void wn_shift(const float* __restrict__ src,
                                                float* __restrict__ dst)
{
    const int warp = threadIdx.x >> 5;
    const unsigned lane = threadIdx.x & 31;
    const size_t base = (size_t)blockIdx.x*8192 + (size_t)warp*2048;  // floats
    const float4* s4 = (const float4*)(src + base);
    float4*       d4 = (float4*)(dst + base);

    float bnd = 0.f;
    if (lane == 31) {
        size_t g = base + 2048;
        bnd = src[g < NBUF ? g : NBUF - 1];   // clamp slot is an insertion col
    }
    float4 A[16];
    #pragma unroll
    for (int r = 0; r < 16; ++r) A[r] = s4[r*32 + lane];

    int col = (int)((base + (size_t)lane*4) % NCOLS);   // col of element 0, r=0

    #pragma unroll
    for (int r = 0; r < 16; ++r) {
        float nd = __shfl_down_sync(0xffffffffu, A[r].x, 1);
        float n0 = (r < 15) ? __shfl_sync(0xffffffffu, A[r+1].x, 0) : bnd;
        float nxt = (lane == 31) ? n0 : nd;
        float4 v = make_float4(A[r].y, A[r].z, A[r].w, nxt);

        int c0 = col, c1 = col+1, c2 = col+2, c3 = col+3;
        if (c1 >= NCOLS) c1 -= NCOLS;
        if (c2 >= NCOLS) c2 -= NCOLS;
        if (c3 >= NCOLS) c3 -= NCOLS;
        bool i0 = ((c0+2) & (c0+1)) == 0;
        bool i1 = ((c1+2) & (c1+1)) == 0;
        bool i2 = ((c2+2) & (c2+1)) == 0;
        bool i3 = ((c3+2) & (c3+1)) == 0;
        if (!(i0 | i1 | i2 | i3)) {
            d4[r*32 + lane] = v;
        } else {
            float* p = (float*)(d4 + r*32 + lane);
            if (!i0) p[0] = v.x;
            if (!i1) p[1] = v.y;
            if (!i2) p[2] = v.z;
            if (!i3) p[3] = v.w;
        }
        col += 128;
        if (col >= NCOLS) col -= NCOLS;
    }
}

extern "C" void kernel_launch(void* const* d_in, const int* in_sizes, int n_in,
                              void* d_out, int out_size)
{
    const float* x     = (const float*)d_in[0];
    const float* buf   = (const float*)d_in[1];
    const float* inp_w = (const float*)d_in[2];
    const float* inp_b = (const float*)d_in[3];
    const float* fw0   = (const float*)d_in[4];
    const float* fw1   = (const float*)d_in[5];
    const float* fb    = (const float*)d_in[6];
    const float* gw0   = (const float*)d_in[7];
    const float* gw1   = (const float*)d_in[8];
    const float* gb    = (const float*)d_in[9];
    const float* rw    = (const float*)d_in[10];
    const float* rb    = (const float*)d_in[11];
    const float* sw    = (const float*)d_in[12];
    const float* sb    = (const float*)d_in[13];
    const float* h1w   = (const float*)d_in[14];
    const float* h1b   = (const float*)d_in[15];
    const float* h2w   = (const float*)d_in[16];
    const float* h2b   = (const float*)d_in[17];

    float* out  = (float*)d_out;            // (2048, 2)
    float* nbuf = out + NBATCH*2;           // (2048, 64, 1023)

    // lazy one-time creation (first call = correctness run, before capture)
    static cudaStream_t s2 = nullptr;
    static cudaEvent_t ev_fork = nullptr, ev_join = nullptr;
    if (!s2) {
        int lo, hi;
        cudaDeviceGetStreamPriorityRange(&lo, &hi);   // lo = LEAST priority
        cudaStreamCreateWithPriority(&s2, cudaStreamNonBlocking, lo);
        cudaEventCreateWithFlags(&ev_fork, cudaEventDisableTiming);
        cudaEventCreateWithFlags(&ev_join, cudaEventDisableTiming);
    }

    const int smem_bytes = (TILE*CURP*(NBLK+2) + 5*4096 + 6144 + 288 + 2*TILE*SSP)
                           * (int)sizeof(float);     // 172672 B
    cudaFuncSetAttribute(wn_compute, cudaFuncAttributeMaxDynamicSharedMemorySize,
                         smem_bytes);

    // fork: compute launched FIRST (grabs its SM slots); shift fills the rest
    cudaEventRecord(ev_fork, 0);
    cudaStreamWaitEvent(s2, ev_fork, 0);

    wn_compute<<<NBATCH/TILE, 128, smem_bytes>>>(
        x, buf, inp_w, inp_b, fw0, fw1, fb, gw0, gw1, gb,
        rw, rb, sw, sb, h1w, h1b, h2w, h2b, out, nbuf);

    wn_shift<<<16368, 128, 0, s2>>>(buf, nbuf);
    cudaEventRecord(ev_join, s2);

    // join: main stream waits for shift so the graph completes both branches
    cudaStreamWaitEvent(0, ev_join, 0);
}

// round 12
// speedup vs baseline: 1.6983x; 1.0012x over previous
#include <cuda_runtime.h>

#define NBLK   10
#define NBATCH 2048
#define NCH    64
#define NSKIP  96
#define TILE   16
#define NCOLS  1023
#define CURP   68                      /* padded row stride for cur/del/z */
#define SSP    100                     /* padded row stride for skip/h */
#define NBUF   ((size_t)NBATCH*NCH*NCOLS)   /* 134086656 */

typedef unsigned long long u64;

__device__ __forceinline__ u64 pk2(float a, float b) {
    u64 r; asm("mov.b64 %0, {%1, %2};" : "=l"(r) : "f"(a), "f"(b)); return r;
}
__device__ __forceinline__ u64 dup2(float a) {
    u64 r; asm("mov.b64 %0, {%1, %1};" : "=l"(r) : "f"(a)); return r;
}
__device__ __forceinline__ u64 fma2p(u64 a, u64 b, u64 c) {
    u64 d; asm("fma.rn.f32x2 %0, %1, %2, %3;" : "=l"(d) : "l"(a), "l"(b), "l"(c));
    return d;
}
__device__ __forceinline__ u64 add2p(u64 a, u64 b) {
    u64 d; asm("add.rn.f32x2 %0, %1, %2;" : "=l"(d) : "l"(a), "l"(b)); return d;
}
__device__ __forceinline__ void up2(u64 v, float& a, float& b) {
    asm("mov.b64 {%0, %1}, %2;" : "=f"(a), "=f"(b) : "l"(v));
}
__device__ __forceinline__ float tanh_ap(float x) {
    float y; asm("tanh.approx.f32 %0, %1;" : "=f"(y) : "f"(x)); return y;
}

// ---------------------------------------------------------------------------
// Compute kernel: 128 CTAs x 128 threads, packed f32x2 FMAs, float4
// activation loads, MUFU tanh. Snapshots written directly to nbuf.
// ---------------------------------------------------------------------------
__global__ __launch_bounds__(128, 1) void wn_compute(
    const float* __restrict__ x,   const float* __restrict__ buf,
    const float* __restrict__ inp_w, const float* __restrict__ inp_b,
    const float* __restrict__ fw0, const float* __restrict__ fw1, const float* __restrict__ fb,
    const float* __restrict__ gw0, const float* __restrict__ gw1, const float* __restrict__ gb,
    const float* __restrict__ rw,  const float* __restrict__ rb,
    const float* __restrict__ sw,  const float* __restrict__ sb,
    const float* __restrict__ h1w, const float* __restrict__ h1b,
    const float* __restrict__ h2w, const float* __restrict__ h2b,
    float* __restrict__ out, float* __restrict__ nbuf)
{
    extern __shared__ float sm[];
    float* cur = sm;                          // 16*68
    float* del = cur + TILE*CURP;             // 10*16*68
    float* zs  = del + NBLK*TILE*CURP;        // 16*68
    float* w0  = zs  + TILE*CURP;             // 4096  (transposed [k][t], row 64)
    float* w1  = w0 + 4096;
    float* w2  = w1 + 4096;
    float* w3  = w2 + 4096;
    float* wrs = w3 + 4096;                   // res weights
    float* wst = wrs + 4096;                  // 64*96 skip weights transposed
    float* bia = wst + 6144;                  // fb[64] gb[64] rb[64] sb[96]
    float* ssm = bia + 288;                   // 16*100 skip sums
    float* hsm = ssm + TILE*SSP;              // 16*100 hidden

    const int tid  = threadIdx.x;
    const int lane = tid & 31, warp = tid >> 5;
    const int sp = tid >> 4, tg = tid & 15;
    const int s0 = sp*2, s1 = s0+1, t0 = tg*4;
    const int bbase = blockIdx.x * TILE;

    // ---- x tile into zs scratch (16 x 32) ----
    for (int idx = tid; idx < TILE*32; idx += 128) {
        int s = idx >> 5, k = idx & 31;
        zs[idx] = x[(bbase+s)*32 + k];
    }
    __syncthreads();

    // ---- input projection: cur = x @ inp_w.T + inp_b ----
    {
        float a0[4], a1[4];
        #pragma unroll
        for (int j = 0; j < 4; ++j) { a0[j] = inp_b[t0+j]; a1[j] = a0[j]; }
        #pragma unroll 8
        for (int k = 0; k < 32; ++k) {
            float x0 = zs[s0*32+k], x1 = zs[s1*32+k];
            #pragma unroll
            for (int j = 0; j < 4; ++j) {
                float w = inp_w[(t0+j)*32 + k];
                a0[j] += x0*w; a1[j] += x1*w;
            }
        }
        #pragma unroll
        for (int j = 0; j < 4; ++j) {
            cur[s0*CURP + t0 + j] = a0[j];
            cur[s1*CURP + t0 + j] = a1[j];
        }
    }

    // ---- preload all delayed taps: del[i][s][c] = buf[b, c, 2^i - 1] ----
    for (int idx = tid; idx < NBLK*TILE*NCH; idx += 128) {
        int i = idx >> 10;
        int r = idx & 1023;
        int s = r >> 6, c = r & 63;
        int off = (1 << i) - 1;
        del[(i*TILE + s)*CURP + c] =
            buf[((size_t)(bbase+s)*NCH + c)*NCOLS + off];
    }

    u64 sa0 = 0ull, sa1 = 0ull, sa2 = 0ull;   // skip sums sample s0 (3 ch-pairs)
    u64 sb0 = 0ull, sb1 = 0ull, sb2 = 0ull;   // sample s1
    const int ts = tg*6;

    for (int i = 0; i < NBLK; ++i) {
        __syncthreads();

        // ---- write current entering block i DIRECTLY to nbuf insertion col
        {
            int jcol = (2 << i) - 2;                  // 2^(i+1)-2
            for (int idx = tid; idx < TILE*NCH; idx += 128) {
                int s = idx >> 6, c = idx & 63;
                nbuf[((size_t)(bbase+s)*NCH + c)*NCOLS + jcol] = cur[s*CURP + c];
            }
        }

        // ---- stage transposed weights for this block ----
        {
            const float* srcs[5] = { fw0 + i*4096, fw1 + i*4096, gw0 + i*4096,
                                     gw1 + i*4096, rw + i*4096 };
            float* dsts[5] = { w0, w1, w2, w3, wrs };
            #pragma unroll
            for (int mm = 0; mm < 5; ++mm) {
                const float* s = srcs[mm]; float* d = dsts[mm];
                #pragma unroll
                for (int th = 0; th < 2; ++th) {
                    int t = th*32 + lane;
                    #pragma unroll
                    for (int kc = 0; kc < 4; ++kc) {
                        int k0 = warp*16 + kc*4;
                        float4 v = *(const float4*)(s + t*64 + k0);
                        d[(k0+0)*64+t] = v.x; d[(k0+1)*64+t] = v.y;
                        d[(k0+2)*64+t] = v.z; d[(k0+3)*64+t] = v.w;
                    }
                }
            }
            const float* s = sw + i*NSKIP*NCH;   // [96][64] -> wst[64][96]
            #pragma unroll
            for (int th = 0; th < 3; ++th) {
                int t = th*32 + lane;
                #pragma unroll
                for (int kc = 0; kc < 4; ++kc) {
                    int k0 = warp*16 + kc*4;
                    float4 v = *(const float4*)(s + t*64 + k0);
                    wst[(k0+0)*96+t] = v.x; wst[(k0+1)*96+t] = v.y;
                    wst[(k0+2)*96+t] = v.z; wst[(k0+3)*96+t] = v.w;
                }
            }
            if (tid < 64) {
                bia[tid]      = fb[i*64+tid];
                bia[64+tid]   = gb[i*64+tid];
                bia[128+tid]  = rb[i*64+tid];
            }
            if (tid < 96) bia[192+tid] = sb[i*NSKIP+tid];
        }
        __syncthreads();

        // ---- f/g GEMMs (packed f32x2, float4 activation loads) ----
        u64 f0a = pk2(bia[t0],   bia[t0+1]),   f0b = pk2(bia[t0+2],   bia[t0+3]);
        u64 f1a = f0a, f1b = f0b;
        u64 g0a = pk2(bia[64+t0],bia[64+t0+1]),g0b = pk2(bia[64+t0+2],bia[64+t0+3]);
        u64 g1a = g0a, g1b = g0b;
        const float* dle = del + i*TILE*CURP;
        #pragma unroll 4
        for (int k4 = 0; k4 < 64; k4 += 4) {
            float4 D0v = *(const float4*)(dle + s0*CURP + k4);
            float4 D1v = *(const float4*)(dle + s1*CURP + k4);
            float4 C0v = *(const float4*)(cur + s0*CURP + k4);
            float4 C1v = *(const float4*)(cur + s1*CURP + k4);
            const float d0s[4] = {D0v.x, D0v.y, D0v.z, D0v.w};
            const float d1s[4] = {D1v.x, D1v.y, D1v.z, D1v.w};
            const float c0s[4] = {C0v.x, C0v.y, C0v.z, C0v.w};
            const float c1s[4] = {C1v.x, C1v.y, C1v.z, C1v.w};
            #pragma unroll
            for (int kk = 0; kk < 4; ++kk) {
                int k = k4 + kk;
                u64 D0 = dup2(d0s[kk]), D1 = dup2(d1s[kk]);
                u64 C0 = dup2(c0s[kk]), C1 = dup2(c1s[kk]);
                ulonglong2 wa = *(const ulonglong2*)(w0 + k*64 + t0);
                ulonglong2 wb = *(const ulonglong2*)(w1 + k*64 + t0);
                ulonglong2 wc = *(const ulonglong2*)(w2 + k*64 + t0);
                ulonglong2 wd = *(const ulonglong2*)(w3 + k*64 + t0);
                f0a = fma2p(D0, wa.x, f0a); f0b = fma2p(D0, wa.y, f0b);
                f0a = fma2p(C0, wb.x, f0a); f0b = fma2p(C0, wb.y, f0b);
                f1a = fma2p(D1, wa.x, f1a); f1b = fma2p(D1, wa.y, f1b);
                f1a = fma2p(C1, wb.x, f1a); f1b = fma2p(C1, wb.y, f1b);
                g0a = fma2p(D0, wc.x, g0a); g0b = fma2p(D0, wc.y, g0b);
                g0a = fma2p(C0, wd.x, g0a); g0b = fma2p(C0, wd.y, g0b);
                g1a = fma2p(D1, wc.x, g1a); g1b = fma2p(D1, wc.y, g1b);
                g1a = fma2p(C1, wd.x, g1a); g1b = fma2p(C1, wd.y, g1b);
            }
        }
        float f0[4], f1[4], g0[4], g1[4];
        up2(f0a, f0[0], f0[1]); up2(f0b, f0[2], f0[3]);
        up2(f1a, f1[0], f1[1]); up2(f1b, f1[2], f1[3]);
        up2(g0a, g0[0], g0[1]); up2(g0b, g0[2], g0[3]);
        up2(g1a, g1[0], g1[1]); up2(g1b, g1[2], g1[3]);

        // ---- z = tanh(f)*sigmoid(g), both via MUFU tanh.approx ----
        float z0[4], z1[4];
        #pragma unroll
        for (int j = 0; j < 4; ++j) {
            z0[j] = tanh_ap(f0[j]) * (0.5f + 0.5f*tanh_ap(0.5f*g0[j]));
            z1[j] = tanh_ap(f1[j]) * (0.5f + 0.5f*tanh_ap(0.5f*g1[j]));
        }
        *(float4*)(zs + s0*CURP + t0) = make_float4(z0[0],z0[1],z0[2],z0[3]);
        *(float4*)(zs + s1*CURP + t0) = make_float4(z1[0],z1[1],z1[2],z1[3]);
        __syncthreads();

        // ---- res + skip GEMMs (packed f32x2, float4 activation loads) ----
        u64 r0a = pk2(bia[128+t0],   bia[128+t0+1]);
        u64 r0b = pk2(bia[128+t0+2], bia[128+t0+3]);
        u64 r1a = r0a, r1b = r0b;
        #pragma unroll 4
        for (int k4 = 0; k4 < 64; k4 += 4) {
            float4 Z0v = *(const float4*)(zs + s0*CURP + k4);
            float4 Z1v = *(const float4*)(zs + s1*CURP + k4);
            const float z0s[4] = {Z0v.x, Z0v.y, Z0v.z, Z0v.w};
            const float z1s[4] = {Z1v.x, Z1v.y, Z1v.z, Z1v.w};
            #pragma unroll
            for (int kk = 0; kk < 4; ++kk) {
                int k = k4 + kk;
                u64 Z0 = dup2(z0s[kk]), Z1 = dup2(z1s[kk]);
                ulonglong2 wv = *(const ulonglong2*)(wrs + k*64 + t0);
                r0a = fma2p(Z0, wv.x, r0a); r0b = fma2p(Z0, wv.y, r0b);
                r1a = fma2p(Z1, wv.x, r1a); r1b = fma2p(Z1, wv.y, r1b);
                const u64* wsk = (const u64*)(wst + k*96 + ts);
                u64 wk0 = wsk[0], wk1 = wsk[1], wk2 = wsk[2];
                sa0 = fma2p(Z0, wk0, sa0); sa1 = fma2p(Z0, wk1, sa1);
                sa2 = fma2p(Z0, wk2, sa2);
                sb0 = fma2p(Z1, wk0, sb0); sb1 = fma2p(Z1, wk1, sb1);
                sb2 = fma2p(Z1, wk2, sb2);
            }
        }
        {   // skip biases for this block
            const u64* bb = (const u64*)(bia + 192 + ts);
            u64 b0 = bb[0], b1 = bb[1], b2 = bb[2];
            sa0 = add2p(sa0, b0); sa1 = add2p(sa1, b1); sa2 = add2p(sa2, b2);
            sb0 = add2p(sb0, b0); sb1 = add2p(sb1, b1); sb2 = add2p(sb2, b2);
        }

        // ---- residual update of current (owner-exclusive) ----
        {
            float r0[4], r1[4];
            up2(r0a, r0[0], r0[1]); up2(r0b, r0[2], r0[3]);
            up2(r1a, r1[0], r1[1]); up2(r1b, r1[2], r1[3]);
            float4 c4 = *(float4*)(cur + s0*CURP + t0);
            c4.x += 0.3f*r0[0]; c4.y += 0.3f*r0[1];
            c4.z += 0.3f*r0[2]; c4.w += 0.3f*r0[3];
            *(float4*)(cur + s0*CURP + t0) = c4;
            float4 d4 = *(float4*)(cur + s1*CURP + t0);
            d4.x += 0.3f*r1[0]; d4.y += 0.3f*r1[1];
            d4.z += 0.3f*r1[2]; d4.w += 0.3f*r1[3];
            *(float4*)(cur + s1*CURP + t0) = d4;
        }
    }

    // ---- head ----
    __syncthreads();
    {
        float ssum0[6], ssum1[6];
        up2(sa0, ssum0[0], ssum0[1]); up2(sa1, ssum0[2], ssum0[3]);
        up2(sa2, ssum0[4], ssum0[5]);
        up2(sb0, ssum1[0], ssum1[1]); up2(sb1, ssum1[2], ssum1[3]);
        up2(sb2, ssum1[4], ssum1[5]);
        #pragma unroll
        for (int j = 0; j < 6; ++j) {
            ssm[s0*SSP + ts + j] = fmaxf(ssum0[j], 0.f);
            ssm[s1*SSP + ts + j] = fmaxf(ssum1[j], 0.f);
        }
    }
    float* h1T = w0;
    for (int idx = tid; idx < NSKIP*NSKIP; idx += 128) {
        int k = idx / 96, t = idx - k*96;
        h1T[idx] = h1w[t*96 + k];
    }
    __syncthreads();
    {
        float a0[6], a1[6];
        #pragma unroll
        for (int j = 0; j < 6; ++j) { a0[j] = h1b[ts+j]; a1[j] = a0[j]; }
        #pragma unroll 4
        for (int k = 0; k < 96; ++k) {
            float u0 = ssm[s0*SSP+k], u1 = ssm[s1*SSP+k];
            const float* wk = h1T + k*96 + ts;
            #pragma unroll
            for (int j = 0; j < 6; ++j) {
                float w = wk[j];
                a0[j] += u0*w; a1[j] += u1*w;
            }
        }
        #pragma unroll
        for (int j = 0; j < 6; ++j) {
            hsm[s0*SSP + ts + j] = fmaxf(a0[j], 0.f);
            hsm[s1*SSP + ts + j] = fmaxf(a1[j], 0.f);
        }
    }
    __syncthreads();
    if (tid < 32) {
        int s = tid >> 1, jj = tid & 1;
        float a = h2b[jj];
        #pragma unroll 4
        for (int k = 0; k < 96; ++k)
            a += hsm[s*SSP+k] * h2w[jj*96+k];
        out[(bbase+s)*2 + jj] = a;
    }
}

// ---------------------------------------------------------------------------
// Shift: dst[n] = src[n+1], fully coalesced, skipping the 10 insertion
// columns per row (col+2 is a power of two <=1024 <=> insertion col).
// 256-thread CTAs (best measured standalone: 84.3% DRAM).
// Grid 8184 x 256 covers NBUF exactly (8184*16384 = 134086656).
// ---------------------------------------------------------------------------
__global__ __launch_bounds__(256) void wn_shift(const float* __restrict__ src,
                                                float* __restrict__ dst)
{
    const int warp = threadIdx.x >> 5;
    const unsigned lane = threadIdx.x & 31;
    const size_t base = (size_t)blockIdx.x*16384 + (size_t)warp*2048;  // floats
    const float4* s4 = (const float4*)(src + base);
    float4*       d4 = (float4*)(dst + base);

    float bnd = 0.f;
    if (lane == 31) {
        size_t g = base + 2048;
        bnd = src[g < NBUF ? g : NBUF - 1];   // clamp slot is an insertion col
    }
    float4 A[16];
    #pragma unroll
    for (int r = 0; r < 16; ++r) A[r] = s4[r*32 + lane];

    int col = (int)((base + (size_t)lane*4) % NCOLS);   // col of element 0, r=0

    #pragma unroll
    for (int r = 0; r < 16; ++r) {
        float nd = __shfl_down_sync(0xffffffffu, A[r].x, 1);
        float n0 = (r < 15) ? __shfl_sync(0xffffffffu, A[r+1].x, 0) : bnd;
        float nxt = (lane == 31) ? n0 : nd;
        float4 v = make_float4(A[r].y, A[r].z, A[r].w, nxt);

        int c0 = col, c1 = col+1, c2 = col+2, c3 = col+3;
        if (c1 >= NCOLS) c1 -= NCOLS;
        if (c2 >= NCOLS) c2 -= NCOLS;
        if (c3 >= NCOLS) c3 -= NCOLS;
        bool i0 = ((c0+2) & (c0+1)) == 0;
        bool i1 = ((c1+2) & (c1+1)) == 0;
        bool i2 = ((c2+2) & (c2+1)) == 0;
        bool i3 = ((c3+2) & (c3+1)) == 0;
        if (!(i0 | i1 | i2 | i3)) {
            d4[r*32 + lane] = v;
        } else {
            float* p = (float*)(d4 + r*32 + lane);
            if (!i0) p[0] = v.x;
            if (!i1) p[1] = v.y;
            if (!i2) p[2] = v.z;
            if (!i3) p[3] = v.w;
        }
        col += 128;
        if (col >= NCOLS) col -= NCOLS;
    }
}

extern "C" void kernel_launch(void* const* d_in, const int* in_sizes, int n_in,
                              void* d_out, int out_size)
{
    const float* x     = (const float*)d_in[0];
    const float* buf   = (const float*)d_in[1];
    const float* inp_w = (const float*)d_in[2];
    const float* inp_b = (const float*)d_in[3];
    const float* fw0   = (const float*)d_in[4];
    const float* fw1   = (const float*)d_in[5];
    const float* fb    = (const float*)d_in[6];
    const float* gw0   = (const float*)d_in[7];
    const float* gw1   = (const float*)d_in[8];
    const float* gb    = (const float*)d_in[9];
    const float* rw    = (const float*)d_in[10];
    const float* rb    = (const float*)d_in[11];
    const float* sw    = (const float*)d_in[12];
    const float* sb    = (const float*)d_in[13];
    const float* h1w   = (const float*)d_in[14];
    const float* h1b   = (const float*)d_in[15];
    const float* h2w   = (const float*)d_in[16];
    const float* h2b   = (const float*)d_in[17];

    float* out  = (float*)d_out;            // (2048, 2)
    float* nbuf = out + NBATCH*2;           // (2048, 64, 1023)

    // lazy one-time creation (first call = correctness run, before capture)
    static cudaStream_t s2 = nullptr;
    static cudaEvent_t ev_fork = nullptr, ev_join = nullptr;
    if (!s2) {
        int lo, hi;
        cudaDeviceGetStreamPriorityRange(&lo, &hi);   // lo = LEAST priority
        cudaStreamCreateWithPriority(&s2, cudaStreamNonBlocking, lo);
        cudaEventCreateWithFlags(&ev_fork, cudaEventDisableTiming);
        cudaEventCreateWithFlags(&ev_join, cudaEventDisableTiming);
    }

    const int smem_bytes = (TILE*CURP*(NBLK+2) + 5*4096 + 6144 + 288 + 2*TILE*SSP)
                           * (int)sizeof(float);     // 172672 B
    cudaFuncSetAttribute(wn_compute, cudaFuncAttributeMaxDynamicSharedMemorySize,
                         smem_bytes);

    // fork: compute launched FIRST (grabs its SM slots); shift fills the rest
    cudaEventRecord(ev_fork, 0);
    cudaStreamWaitEvent(s2, ev_fork, 0);

    wn_compute<<<NBATCH/TILE, 128, smem_bytes>>>(
        x, buf, inp_w, inp_b, fw0, fw1, fb, gw0, gw1, gb,
        rw, rb, sw, sb, h1w, h1b, h2w, h2b, out, nbuf);

    wn_shift<<<8184, 256, 0, s2>>>(buf, nbuf);
    cudaEventRecord(ev_join, s2);

    // join: main stream waits for shift so the graph completes both branches
    cudaStreamWaitEvent(0, ev_join, 0);
}